// round 1
// baseline (speedup 1.0000x reference)
#include <cuda_runtime.h>
#include <cstdint>
#include <cstddef>

// Problem constants (fixed by the dataset)
#define B_TOT 4096
#define C_IN  512
#define O_TOT 1024
#define DD    10
#define LL    1024

// Tiling
#define BT         32          // b-rows per CTA
#define O_PER_CTA  128         // o's per CTA  -> grid (128, 8)
#define OCHUNK     64          // o's staged between output flushes
#define XS_PITCH   33          // x slice pitch (bank-conflict-free gathers)
#define ST_PITCH   65          // output stage pitch
#define SMEM_FLOATS (C_IN * XS_PITCH + BT * ST_PITCH)
#define SMEM_BYTES  (SMEM_FLOATS * 4)

// Repacked (16B-aligned, padded to 12) thresholds / ordinals
__device__ float4 g_thp[O_TOT * 3];
__device__ int4   g_ordp[O_TOT * 3];

// Prologue: detect ordinals dtype (int64 vs int32) by value-range test,
// then repack thresholds+ordinals into aligned float4/int4 blocks of 12.
__global__ void convert_kernel(const float* __restrict__ th,
                               const void*  __restrict__ ord_raw) {
    __shared__ int is64_s;
    if (threadIdx.x == 0) {
        // If the data were int32, reading int64 pairs gives v0 + v1*2^32 with
        // v1 a random ordinal in [0,512): P(all 16 look like valid int64) ~ 1e-43.
        const long long* p = (const long long*)ord_raw;
        int ok = 1;
        for (int i = 0; i < 16; i++) {
            long long v = p[i];
            if (v < 0 || v >= C_IN) ok = 0;
        }
        is64_s = ok;
    }
    __syncthreads();
    const int use64 = is64_s;
    const long long* p64 = (const long long*)ord_raw;
    const int*       p32 = (const int*)ord_raw;
    float* thf = (float*)g_thp;
    int*   odf = (int*)g_ordp;
    for (int j = threadIdx.x; j < O_TOT * 12; j += blockDim.x) {
        int o = j / 12, k = j % 12;
        float tv = 0.0f;
        int   ov = 0;
        if (k < DD) {
            tv = th[o * DD + k];
            ov = use64 ? (int)p64[o * DD + k] : p32[o * DD + k];
        }
        thf[j] = tv;
        odf[j] = ov;
    }
}

__global__ __launch_bounds__(256) void fern_kernel(const float* __restrict__ x,
                                                   const float* __restrict__ wts,
                                                   float* __restrict__ out) {
    extern __shared__ float sm[];
    float* xs    = sm;                     // [C_IN][XS_PITCH] : xs[c*33 + b]
    float* stage = sm + C_IN * XS_PITCH;   // [BT][ST_PITCH]

    const int tid  = threadIdx.x;
    const int lane = tid & 31;   // = local b index
    const int warp = tid >> 5;   // 8 warps
    const int b0      = blockIdx.x * BT;
    const int o_begin = blockIdx.y * O_PER_CTA;

    // Stage x[b0:b0+32, :] into smem, channel-major with pitch 33.
    // Global reads: 128B coalesced per warp. Smem writes: banks (c+r)%32, conflict-free.
    for (int r = warp; r < BT; r += 8) {
        const float* xrow = x + (size_t)(b0 + r) * C_IN;
        for (int c = lane; c < C_IN; c += 32)
            xs[c * XS_PITCH + r] = xrow[c];
    }
    __syncthreads();

    for (int oc = o_begin; oc < o_begin + O_PER_CTA; oc += OCHUNK) {
        // Each warp handles OCHUNK/8 = 8 consecutive o's; lane = b.
        #pragma unroll 1
        for (int i = 0; i < OCHUNK / 8; i++) {
            const int o = oc + warp * (OCHUNK / 8) + i;

            float thv[12];
            int   odv[12];
            ((float4*)thv)[0] = g_thp[o * 3 + 0];
            ((float4*)thv)[1] = g_thp[o * 3 + 1];
            ((float4*)thv)[2] = g_thp[o * 3 + 2];
            ((int4*)odv)[0]   = g_ordp[o * 3 + 0];
            ((int4*)odv)[1]   = g_ordp[o * 3 + 1];
            ((int4*)odv)[2]   = g_ordp[o * 3 + 2];

            float minm = 3.0e38f;
            int   leaf = 0;
            #pragma unroll
            for (int d = 0; d < DD; d++) {
                // All lanes share odv[d]; addresses differ only in lane -> bank-conflict-free.
                float m = xs[odv[d] * XS_PITCH + lane] - thv[d];
                leaf = (leaf << 1) | (m > 0.0f ? 1 : 0);
                minm = fminf(minm, fabsf(m));
            }
            // Data-dependent gather in the 4KB weights row (L2-resident).
            float wv = __ldg(wts + (size_t)o * LL + leaf);
            // Bank-conflict-free: banks = (lane*65)%32 = lane.
            stage[lane * ST_PITCH + (o - oc)] = wv * minm;
        }
        __syncthreads();

        // Flush 32 x 64 staged outputs as coalesced float4 rows.
        for (int idx = tid; idx < BT * (OCHUNK / 4); idx += 256) {
            int bl = idx / (OCHUNK / 4);
            int og = (idx % (OCHUNK / 4)) * 4;
            float4 v;
            v.x = stage[bl * ST_PITCH + og + 0];
            v.y = stage[bl * ST_PITCH + og + 1];
            v.z = stage[bl * ST_PITCH + og + 2];
            v.w = stage[bl * ST_PITCH + og + 3];
            *(float4*)(out + (size_t)(b0 + bl) * O_TOT + (oc + og)) = v;
        }
        __syncthreads();
    }
}

extern "C" void kernel_launch(void* const* d_in, const int* in_sizes, int n_in,
                              void* d_out, int out_size) {
    (void)in_sizes; (void)n_in; (void)out_size;
    const float* x   = (const float*)d_in[0];
    const float* th  = (const float*)d_in[1];
    const void*  ord = d_in[2];
    const float* wts = (const float*)d_in[3];
    float* out = (float*)d_out;

    convert_kernel<<<1, 256>>>(th, ord);

    cudaFuncSetAttribute(fern_kernel,
                         cudaFuncAttributeMaxDynamicSharedMemorySize, SMEM_BYTES);
    dim3 grid(B_TOT / BT, O_TOT / O_PER_CTA);   // (128, 8)
    fern_kernel<<<grid, 256, SMEM_BYTES>>>(x, wts, out);
}

// round 2
// speedup vs baseline: 1.2868x; 1.2868x over previous
#include <cuda_runtime.h>
#include <cstdint>
#include <cstddef>

// Problem constants (fixed by the dataset)
#define B_TOT 4096
#define C_IN  512
#define O_TOT 1024
#define DD    10
#define LL    1024

// Tiling
#define BT         32          // b-rows per CTA (lane = local b)
#define O_PER_CTA  128         // o's per CTA -> grid (128, 8)
#define OCHUNK     64          // o's staged between output flushes
#define ST_PITCH   68          // output stage pitch (16B-aligned rows, conflict-free)
#define SMEM_FLOATS (C_IN * 32 + BT * ST_PITCH)
#define SMEM_BYTES  (SMEM_FLOATS * 4)

// xs swizzle: storage index for (channel c, local-b b).
// Gather (c fixed, b=lane):   bank = lane ^ f(c)      -> permutation, conflict-free
// Staging (b=r fixed, c=lane*4+k): f(c) = c>>2 = lane -> bank = r ^ lane, conflict-free
#define XS_IDX(c, b) (((c) << 5) | ((b) ^ (((c) >> 2) & 31)))

// Repacked (16B-aligned, padded to 12) thresholds / ordinals
__device__ float4 g_thp[O_TOT * 3];
__device__ int4   g_ordp[O_TOT * 3];

// Prologue: detect ordinals dtype (int64 vs int32) by value-range test,
// then repack thresholds+ordinals into aligned float4/int4 blocks of 12.
__global__ void convert_kernel(const float* __restrict__ th,
                               const void*  __restrict__ ord_raw) {
    __shared__ int is64_s;
    if (threadIdx.x == 0) {
        // int32 data read as int64 pairs gives v0 + v1*2^32 with v1 in [0,512):
        // P(16 such values all land in [0,512)) ~ 1e-43.
        const long long* p = (const long long*)ord_raw;
        int ok = 1;
        for (int i = 0; i < 16; i++) {
            long long v = p[i];
            if (v < 0 || v >= C_IN) ok = 0;
        }
        is64_s = ok;
    }
    __syncthreads();
    const int use64 = is64_s;
    const long long* p64 = (const long long*)ord_raw;
    const int*       p32 = (const int*)ord_raw;
    float* thf = (float*)g_thp;
    int*   odf = (int*)g_ordp;
    for (int j = blockIdx.x * blockDim.x + threadIdx.x; j < O_TOT * 12;
         j += gridDim.x * blockDim.x) {
        int o = j / 12, k = j % 12;
        float tv = 0.0f;
        int   ov = 0;
        if (k < DD) {
            tv = th[o * DD + k];
            ov = use64 ? (int)p64[o * DD + k] : p32[o * DD + k];
        }
        thf[j] = tv;
        odf[j] = ov;
    }
}

__global__ __launch_bounds__(256) void fern_kernel(const float* __restrict__ x,
                                                   const float* __restrict__ wts,
                                                   float* __restrict__ out) {
    extern __shared__ float sm[];
    float* xs    = sm;                  // swizzled [C_IN][32]
    float* stage = sm + C_IN * 32;      // [BT][ST_PITCH]

    const int tid  = threadIdx.x;
    const int lane = tid & 31;   // = local b index
    const int warp = tid >> 5;   // 8 warps
    const int b0      = blockIdx.x * BT;
    const int o_begin = blockIdx.y * O_PER_CTA;

    // Stage x[b0:b0+32, :] into swizzled smem. LDG.128 coalesced; STS conflict-free.
    for (int r = warp; r < BT; r += 8) {
        const float4* xrow = (const float4*)(x + (size_t)(b0 + r) * C_IN);
        for (int c4 = lane; c4 < C_IN / 4; c4 += 32) {
            float4 v = xrow[c4];
            int c = c4 * 4;
            xs[XS_IDX(c + 0, r)] = v.x;
            xs[XS_IDX(c + 1, r)] = v.y;
            xs[XS_IDX(c + 2, r)] = v.z;
            xs[XS_IDX(c + 3, r)] = v.w;
        }
    }
    __syncthreads();

    for (int oc = o_begin; oc < o_begin + O_PER_CTA; oc += OCHUNK) {
        const int obase = oc + (warp << 3);   // 8 consecutive o's per warp

        // Phase 1: all 8 (leaf, minm) — 80 independent LDS in flight.
        int   leaf_a[8];
        float minm_a[8];
        #pragma unroll
        for (int i = 0; i < 8; i++) {
            const int o = obase + i;
            float4 t0 = g_thp[o * 3 + 0];
            float4 t1 = g_thp[o * 3 + 1];
            float4 t2 = g_thp[o * 3 + 2];
            int4   c0 = g_ordp[o * 3 + 0];
            int4   c1 = g_ordp[o * 3 + 1];
            int4   c2 = g_ordp[o * 3 + 2];

            int leaf = 0;
            float mn = 3.0e38f;
            float m;
            #define STEPX(cc, tt)                                   \
                m = xs[XS_IDX((cc), lane)] - (tt);                  \
                leaf = (leaf << 1) | (m > 0.0f ? 1 : 0);            \
                mn = fminf(mn, fabsf(m));
            STEPX(c0.x, t0.x); STEPX(c0.y, t0.y);
            STEPX(c0.z, t0.z); STEPX(c0.w, t0.w);
            STEPX(c1.x, t1.x); STEPX(c1.y, t1.y);
            STEPX(c1.z, t1.z); STEPX(c1.w, t1.w);
            STEPX(c2.x, t2.x); STEPX(c2.y, t2.y);
            #undef STEPX
            leaf_a[i] = leaf;
            minm_a[i] = mn;
        }

        // Phase 2: 8 independent data-dependent weight gathers in flight.
        float wv[8];
        #pragma unroll
        for (int i = 0; i < 8; i++)
            wv[i] = __ldg(wts + (size_t)(obase + i) * LL + leaf_a[i]);

        // Phase 3: pack and stage (two STS.128, conflict-free with pitch 68).
        float4 s0, s1;
        s0.x = wv[0] * minm_a[0]; s0.y = wv[1] * minm_a[1];
        s0.z = wv[2] * minm_a[2]; s0.w = wv[3] * minm_a[3];
        s1.x = wv[4] * minm_a[4]; s1.y = wv[5] * minm_a[5];
        s1.z = wv[6] * minm_a[6]; s1.w = wv[7] * minm_a[7];
        float4* sp = (float4*)&stage[lane * ST_PITCH + (obase - oc)];
        sp[0] = s0;
        sp[1] = s1;
        __syncthreads();

        // Flush 32 x 64 staged outputs as coalesced float4 rows.
        for (int idx = tid; idx < BT * (OCHUNK / 4); idx += 256) {
            int bl = idx / (OCHUNK / 4);
            int og = (idx % (OCHUNK / 4)) * 4;
            float4 v = *(const float4*)&stage[bl * ST_PITCH + og];
            *(float4*)(out + (size_t)(b0 + bl) * O_TOT + (oc + og)) = v;
        }
        __syncthreads();
    }
}

extern "C" void kernel_launch(void* const* d_in, const int* in_sizes, int n_in,
                              void* d_out, int out_size) {
    (void)in_sizes; (void)n_in; (void)out_size;
    const float* x   = (const float*)d_in[0];
    const float* th  = (const float*)d_in[1];
    const void*  ord = d_in[2];
    const float* wts = (const float*)d_in[3];
    float* out = (float*)d_out;

    convert_kernel<<<48, 256>>>(th, ord);

    cudaFuncSetAttribute(fern_kernel,
                         cudaFuncAttributeMaxDynamicSharedMemorySize, SMEM_BYTES);
    dim3 grid(B_TOT / BT, O_TOT / O_PER_CTA);   // (128, 8)
    fern_kernel<<<grid, 256, SMEM_BYTES>>>(x, wts, out);
}

// round 4
// speedup vs baseline: 1.5630x; 1.2146x over previous
#include <cuda_runtime.h>
#include <cstdint>
#include <cstddef>

// Problem constants (fixed by the dataset)
#define B_TOT 4096
#define C_IN  512
#define O_TOT 1024
#define DD    10
#define LL    1024

// Tiling
#define BT         32          // b-rows per CTA (lane = local b)
#define NTHREADS   512         // 16 warps per CTA
#define O_PER_CTA  128         // o's per CTA -> grid (128, 8)
#define OCHUNK     64          // o's staged between output flushes (4 o's/warp)
#define XS_PITCH   33          // x slice pitch: xs[c*33 + b], conflict-free both ways
#define ST_PITCH   68          // output stage pitch: 272B rows -> 16B-aligned float4,
                               // conflict-free STS.128 and LDS.128 (8-lane phases)
#define SMEM_FLOATS (C_IN * XS_PITCH + BT * ST_PITCH)
#define SMEM_BYTES  (SMEM_FLOATS * 4)

// Repacked (16B-aligned, padded to 12) thresholds / PRE-SCALED ordinals (ord*33)
__device__ float4 g_thp[O_TOT * 3];
__device__ int4   g_ordp[O_TOT * 3];

// Prologue: detect ordinals dtype (int64 vs int32) by value-range test,
// repack thresholds, and pre-scale ordinals by XS_PITCH.
__global__ void convert_kernel(const float* __restrict__ th,
                               const void*  __restrict__ ord_raw) {
    __shared__ int is64_s;
    if (threadIdx.x == 0) {
        // int32 data read as int64 pairs gives v0 + v1*2^32 with v1 in [0,512):
        // P(16 such values all land in [0,512)) ~ 1e-43.
        const long long* p = (const long long*)ord_raw;
        int ok = 1;
        for (int i = 0; i < 16; i++) {
            long long v = p[i];
            if (v < 0 || v >= C_IN) ok = 0;
        }
        is64_s = ok;
    }
    __syncthreads();
    const int use64 = is64_s;
    const long long* p64 = (const long long*)ord_raw;
    const int*       p32 = (const int*)ord_raw;
    float* thf = (float*)g_thp;
    int*   odf = (int*)g_ordp;
    for (int j = blockIdx.x * blockDim.x + threadIdx.x; j < O_TOT * 12;
         j += gridDim.x * blockDim.x) {
        int o = j / 12, k = j % 12;
        float tv = 0.0f;
        int   ov = 0;
        if (k < DD) {
            tv = th[o * DD + k];
            ov = (use64 ? (int)p64[o * DD + k] : p32[o * DD + k]) * XS_PITCH;
        }
        thf[j] = tv;
        odf[j] = ov;
    }
}

__global__ __launch_bounds__(NTHREADS, 3)
void fern_kernel(const float* __restrict__ x,
                 const float* __restrict__ wts,
                 float* __restrict__ out) {
    extern __shared__ float sm[];
    float* xs    = sm;                         // [C_IN][XS_PITCH]
    float* stage = sm + C_IN * XS_PITCH;       // [BT][ST_PITCH]

    const int tid  = threadIdx.x;
    const int lane = tid & 31;   // = local b index
    const int warp = tid >> 5;   // 16 warps
    const int b0      = blockIdx.x * BT;
    const int o_begin = blockIdx.y * O_PER_CTA;

    // Stage x[b0:b0+32, :] channel-major, pitch 33.
    // LDG: consecutive lanes read consecutive floats -> coalesced.
    // STS: banks (33c + r)%32 = (c + r)%32, c = lane + 32k -> permutation, conflict-free.
    for (int r = warp; r < BT; r += 16) {
        const float* xrow = x + (size_t)(b0 + r) * C_IN;
        for (int c = lane; c < C_IN; c += 32)
            xs[c * XS_PITCH + r] = xrow[c];
    }
    __syncthreads();

    const float* xsl = xs + lane;   // per-lane base; gathers become IMAD+LDS
    const float4* __restrict__ thp  = g_thp;
    const int4*   __restrict__ ordp = g_ordp;

    for (int oc = o_begin; oc < o_begin + O_PER_CTA; oc += OCHUNK) {
        const int obase = oc + (warp << 2);   // 4 consecutive o's per warp

        // Phase 1: 4 (leaf, minm) pairs -- 40 independent LDS in flight.
        int   leaf_a[4];
        float minm_a[4];
        #pragma unroll
        for (int i = 0; i < 4; i++) {
            const int o = obase + i;
            float4 t0 = thp[o * 3 + 0];
            float4 t1 = thp[o * 3 + 1];
            float4 t2 = thp[o * 3 + 2];
            int4   c0 = ordp[o * 3 + 0];
            int4   c1 = ordp[o * 3 + 1];
            int4   c2 = ordp[o * 3 + 2];

            int leaf = 0;
            float mn = 3.0e38f;
            float m;
            #define STEPX(cc, tt)                                   \
                m = xsl[(cc)] - (tt);                               \
                leaf = (leaf << 1) | (m > 0.0f ? 1 : 0);            \
                mn = fminf(mn, fabsf(m));
            STEPX(c0.x, t0.x); STEPX(c0.y, t0.y);
            STEPX(c0.z, t0.z); STEPX(c0.w, t0.w);
            STEPX(c1.x, t1.x); STEPX(c1.y, t1.y);
            STEPX(c1.z, t1.z); STEPX(c1.w, t1.w);
            STEPX(c2.x, t2.x); STEPX(c2.y, t2.y);
            #undef STEPX
            leaf_a[i] = leaf;
            minm_a[i] = mn;
        }

        // Phase 2: 4 independent data-dependent weight gathers in flight.
        const float* wbase = wts + (size_t)obase * LL;
        float wv[4];
        #pragma unroll
        for (int i = 0; i < 4; i++)
            wv[i] = __ldg(wbase + i * LL + leaf_a[i]);

        // Phase 3: pack and stage (one STS.128 per thread, conflict-free, aligned).
        float4 s0;
        s0.x = wv[0] * minm_a[0]; s0.y = wv[1] * minm_a[1];
        s0.z = wv[2] * minm_a[2]; s0.w = wv[3] * minm_a[3];
        *(float4*)&stage[lane * ST_PITCH + (obase - oc)] = s0;
        __syncthreads();

        // Flush 32 x 64 staged outputs as coalesced float4 rows (1 per thread).
        {
            int bl = tid >> 4;               // 0..31
            int og = (tid & 15) * 4;         // 0..60
            float4 v = *(const float4*)&stage[bl * ST_PITCH + og];
            *(float4*)(out + (size_t)(b0 + bl) * O_TOT + (oc + og)) = v;
        }
        __syncthreads();
    }
}

extern "C" void kernel_launch(void* const* d_in, const int* in_sizes, int n_in,
                              void* d_out, int out_size) {
    (void)in_sizes; (void)n_in; (void)out_size;
    const float* x   = (const float*)d_in[0];
    const float* th  = (const float*)d_in[1];
    const void*  ord = d_in[2];
    const float* wts = (const float*)d_in[3];
    float* out = (float*)d_out;

    convert_kernel<<<48, 256>>>(th, ord);

    cudaFuncSetAttribute(fern_kernel,
                         cudaFuncAttributeMaxDynamicSharedMemorySize, SMEM_BYTES);
    dim3 grid(B_TOT / BT, O_TOT / O_PER_CTA);   // (128, 8)
    fern_kernel<<<grid, NTHREADS, SMEM_BYTES>>>(x, wts, out);
}

// round 5
// speedup vs baseline: 1.8972x; 1.2138x over previous
#include <cuda_runtime.h>
#include <cstdint>
#include <cstddef>

// Problem constants (fixed by the dataset)
#define B_TOT 4096
#define C_IN  512
#define O_TOT 1024
#define DD    10
#define LL    1024

// Tiling
#define OT        16                 // o's per CTA (one per warp)
#define NB        8                  // b-splits -> grid (8, 64)
#define B_PER_CTA (B_TOT / NB)       // 512 b's per CTA
#define NTHREADS  512
#define ST_PITCH  17                 // stage pitch (conflict-free STS; 1 dup bank on flush)
#define W_SM_FLOATS (OT * LL)        // 16384 floats = 64KB staged weights
#define SMEM_FLOATS (W_SM_FLOATS + 64 * ST_PITCH)
#define SMEM_BYTES  (SMEM_FLOATS * 4)

// Scratch: transposed x (xt[c][b]) so per-warp gathers are coalesced 128B lines.
__device__ float g_xt[(size_t)C_IN * B_TOT];
// Repacked thresholds / ordinals (ordinals pre-scaled by B_TOT)
__device__ float4 g_thp[O_TOT * 3];
__device__ int4   g_ordp[O_TOT * 3];

#define TRANS_BLOCKS ((C_IN / 32) * (B_TOT / 32))   // 16*128 = 2048
#define CONV_BLOCKS  48                             // 48*256 = 12288 = O_TOT*12

// Merged prologue: [0,2048) transpose x -> g_xt ; [2048,2096) repack params.
__global__ void prep_kernel(const float* __restrict__ x,
                            const float* __restrict__ th,
                            const void*  __restrict__ ord_raw) {
    if (blockIdx.x < TRANS_BLOCKS) {
        __shared__ float t[32][33];
        const int tb = blockIdx.x;
        const int cb = tb & (C_IN / 32 - 1);   // channel tile 0..15
        const int bb = tb >> 4;                // b tile 0..127
        const int lane = threadIdx.x & 31, w = threadIdx.x >> 5;
        #pragma unroll
        for (int r = w; r < 32; r += 8)
            t[r][lane] = x[(size_t)(bb * 32 + r) * C_IN + cb * 32 + lane];
        __syncthreads();
        #pragma unroll
        for (int r = w; r < 32; r += 8)
            g_xt[(size_t)(cb * 32 + r) * B_TOT + bb * 32 + lane] = t[lane][r];
    } else {
        // Detect ordinals dtype (int64 vs int32) by value-range test.
        __shared__ int is64_s;
        if (threadIdx.x == 0) {
            const long long* p = (const long long*)ord_raw;
            int ok = 1;
            for (int i = 0; i < 16; i++) {
                long long v = p[i];
                if (v < 0 || v >= C_IN) ok = 0;
            }
            is64_s = ok;
        }
        __syncthreads();
        const int use64 = is64_s;
        const long long* p64 = (const long long*)ord_raw;
        const int*       p32 = (const int*)ord_raw;
        float* thf = (float*)g_thp;
        int*   odf = (int*)g_ordp;
        int j = (blockIdx.x - TRANS_BLOCKS) * blockDim.x + threadIdx.x;
        if (j < O_TOT * 12) {
            int o = j / 12, k = j % 12;
            float tv = 0.0f;
            int   ov = 0;
            if (k < DD) {
                tv = th[o * DD + k];
                ov = (use64 ? (int)p64[o * DD + k] : p32[o * DD + k]) * B_TOT;
            }
            thf[j] = tv;
            odf[j] = ov;
        }
    }
}

__global__ __launch_bounds__(NTHREADS, 2)
void fern_kernel(const float* __restrict__ wts, float* __restrict__ out) {
    extern __shared__ float sm[];
    float* wsm   = sm;                  // [OT][LL] staged weights (64KB)
    float* stage = sm + W_SM_FLOATS;    // [64][ST_PITCH] output stage

    const int tid  = threadIdx.x;
    const int lane = tid & 31;          // b within tile
    const int warp = tid >> 5;          // o within CTA (fixed!)
    const int o_begin = blockIdx.y * OT;
    const int bbase   = blockIdx.x * B_PER_CTA;

    // Stage weights [o_begin : o_begin+16] into smem. 4096 float4 / 512 thr = 8 each.
    {
        const float4* src = (const float4*)(wts + (size_t)o_begin * LL);
        float4* dst = (float4*)wsm;
        #pragma unroll
        for (int i = 0; i < W_SM_FLOATS / 4 / NTHREADS; i++)
            dst[tid + i * NTHREADS] = src[tid + i * NTHREADS];
    }

    // Per-warp params, loaded ONCE (o fixed for entire CTA lifetime).
    const int o = o_begin + warp;
    const float4 t0 = g_thp[o * 3 + 0];
    const float4 t1 = g_thp[o * 3 + 1];
    const float4 t2 = g_thp[o * 3 + 2];
    const int4   c0 = g_ordp[o * 3 + 0];
    const int4   c1 = g_ordp[o * 3 + 1];
    const int4   c2 = g_ordp[o * 3 + 2];

    // 10 base pointers: gathers become LDG [Rp + imm] on coalesced 128B lines.
    const float* xb  = g_xt + bbase + lane;
    const float* xp0 = xb + c0.x;  const float* xp1 = xb + c0.y;
    const float* xp2 = xb + c0.z;  const float* xp3 = xb + c0.w;
    const float* xp4 = xb + c1.x;  const float* xp5 = xb + c1.y;
    const float* xp6 = xb + c1.z;  const float* xp7 = xb + c1.w;
    const float* xp8 = xb + c2.x;  const float* xp9 = xb + c2.y;
    const float* wrow = wsm + (warp << 10);

    __syncthreads();   // weights staged

    #pragma unroll
    for (int itp = 0; itp < B_PER_CTA / 64; itp++) {     // 8 iterations
        #pragma unroll
        for (int half = 0; half < 2; half++) {
            const int off = itp * 64 + half * 32;        // compile-time constant
            // 10 independent coalesced LDGs (L2-resident) in flight.
            float m0 = xp0[off] - t0.x;
            float m1 = xp1[off] - t0.y;
            float m2 = xp2[off] - t0.z;
            float m3 = xp3[off] - t0.w;
            float m4 = xp4[off] - t1.x;
            float m5 = xp5[off] - t1.y;
            float m6 = xp6[off] - t1.z;
            float m7 = xp7[off] - t1.w;
            float m8 = xp8[off] - t2.x;
            float m9 = xp9[off] - t2.y;

            int leaf = ((m0 > 0.0f) << 9) | ((m1 > 0.0f) << 8) |
                       ((m2 > 0.0f) << 7) | ((m3 > 0.0f) << 6) |
                       ((m4 > 0.0f) << 5) | ((m5 > 0.0f) << 4) |
                       ((m6 > 0.0f) << 3) | ((m7 > 0.0f) << 2) |
                       ((m8 > 0.0f) << 1) |  (m9 > 0.0f);

            // Balanced min tree (min is exact -> order-independent).
            float mn = fminf(
                fminf(fminf(fminf(fabsf(m0), fabsf(m1)), fminf(fabsf(m2), fabsf(m3))),
                      fminf(fminf(fabsf(m4), fabsf(m5)), fminf(fabsf(m6), fabsf(m7)))),
                fminf(fabsf(m8), fabsf(m9)));

            // Divergent gather now hits SMEM: ~3.4 avg bank-conflict cycles vs ~28 L1 wf.
            float r = wrow[leaf] * mn;
            stage[(half * 32 + lane) * ST_PITCH + warp] = r;
        }
        __syncthreads();
        // Flush 64 b-rows x 16 o's; each thread 2 elements, 64B coalesced segments.
        {
            const int bl = tid >> 4, oo = tid & 15;
            const int bg = bbase + itp * 64;
            out[(size_t)(bg + bl) * O_TOT + o_begin + oo] =
                stage[bl * ST_PITCH + oo];
            out[(size_t)(bg + bl + 32) * O_TOT + o_begin + oo] =
                stage[(bl + 32) * ST_PITCH + oo];
        }
        __syncthreads();
    }
}

extern "C" void kernel_launch(void* const* d_in, const int* in_sizes, int n_in,
                              void* d_out, int out_size) {
    (void)in_sizes; (void)n_in; (void)out_size;
    const float* x   = (const float*)d_in[0];
    const float* th  = (const float*)d_in[1];
    const void*  ord = d_in[2];
    const float* wts = (const float*)d_in[3];
    float* out = (float*)d_out;

    prep_kernel<<<TRANS_BLOCKS + CONV_BLOCKS, 256>>>(x, th, ord);

    cudaFuncSetAttribute(fern_kernel,
                         cudaFuncAttributeMaxDynamicSharedMemorySize, SMEM_BYTES);
    dim3 grid(NB, O_TOT / OT);   // (8, 64)
    fern_kernel<<<grid, NTHREADS, SMEM_BYTES>>>(wts, out);
}